// round 14
// baseline (speedup 1.0000x reference)
#include <cuda_runtime.h>
#include <cuda_fp16.h>
#include <cstdint>
#include <math.h>

// Problem constants
#define B_     2
#define T_     2048
#define CMODEL 1024
#define NHEADS 16
#define DHEAD  64
#define NTOK   (B_ * T_)          // 4096
#define F3     (3 * CMODEL)       // 3072

// Scratch (fp16)
__device__ __align__(256) __half g_qkvh[NTOK * F3];       // GEMM1 out, q pre-scaled
__device__ __align__(256) __half g_attnh[NTOK * CMODEL];  // attention out
__device__ __align__(256) __half g_xh[NTOK * CMODEL];
__device__ __align__(256) __half g_wqh[F3 * CMODEL];
__device__ __align__(256) __half g_woh[CMODEL * CMODEL];

// Q pre-scale: (1/sqrt(64)) * log2(e)  -> scores land in log2 domain
#define QSCALE 0.18033688011112042f

#define NSM 148

// ---------------------------------------------------------------------------
// Helpers
// ---------------------------------------------------------------------------
__device__ __forceinline__ uint32_t smem_u32(const void* p) {
    uint32_t a;
    asm("{ .reg .u64 t; cvta.to.shared.u64 t, %1; cvt.u32.u64 %0, t; }"
        : "=r"(a) : "l"(p));
    return a;
}
__device__ __forceinline__ void cp16(uint32_t dst, const void* src) {
    asm volatile("cp.async.cg.shared.global [%0], [%1], 16;" :: "r"(dst), "l"(src));
}
#define CP_COMMIT() asm volatile("cp.async.commit_group;" ::: "memory")
#define CP_WAIT0()  asm volatile("cp.async.wait_group 0;" ::: "memory")
#define CP_WAIT1()  asm volatile("cp.async.wait_group 1;" ::: "memory")

__device__ __forceinline__ void mma_f16(float* c, const uint32_t* a, const uint32_t* b) {
    asm volatile(
        "mma.sync.aligned.m16n8k16.row.col.f32.f16.f16.f32 "
        "{%0,%1,%2,%3}, {%4,%5,%6,%7}, {%8,%9}, {%0,%1,%2,%3};"
        : "+f"(c[0]), "+f"(c[1]), "+f"(c[2]), "+f"(c[3])
        : "r"(a[0]), "r"(a[1]), "r"(a[2]), "r"(a[3]), "r"(b[0]), "r"(b[1]));
}
__device__ __forceinline__ void ldsm_x4_trans(uint32_t* r, uint32_t addr) {
    asm volatile("ldmatrix.sync.aligned.m8n8.x4.trans.shared.b16 {%0,%1,%2,%3}, [%4];"
                 : "=r"(r[0]), "=r"(r[1]), "=r"(r[2]), "=r"(r[3]) : "r"(addr));
}
__device__ __forceinline__ uint32_t h2u(__half2 h) {
    uint32_t u; *reinterpret_cast<__half2*>(&u) = h; return u;
}
__device__ __forceinline__ float fexp2(float x) {
    float r;
    asm("ex2.approx.f32 %0, %1;" : "=f"(r) : "f"(x));
    return r;
}

// ---------------------------------------------------------------------------
// Pre-round pass: fp32 inputs -> fp16 copies
// ---------------------------------------------------------------------------
__global__ __launch_bounds__(256) void round_f16_kernel(
    const float4* __restrict__ a, uint2* __restrict__ da, int na4,
    const float4* __restrict__ b, uint2* __restrict__ db, int nb4,
    const float4* __restrict__ c, uint2* __restrict__ dc, int nc4)
{
    int total = na4 + nb4 + nc4;
    for (int i = blockIdx.x * blockDim.x + threadIdx.x; i < total;
         i += gridDim.x * blockDim.x) {
        const float4* s; uint2* d; int j;
        if (i < na4)            { s = a; d = da; j = i; }
        else if (i < na4 + nb4) { s = b; d = db; j = i - na4; }
        else                    { s = c; d = dc; j = i - na4 - nb4; }
        float4 v = s[j];
        d[j] = make_uint2(h2u(__floats2half2_rn(v.x, v.y)),
                          h2u(__floats2half2_rn(v.z, v.w)));
    }
}

// ---------------------------------------------------------------------------
// fp16 GEMM: C[M,N] = A[M,K] * B[N,K]^T, fp32 accum.
// R8-proven per-tile shape: CTA 128x256, 256 threads / 8 warps (warp tile
// 64x64), BK=64, 3-stage cp.async, scalar-LDS fragments.
// NEW: persistent CTAs — grid = min(tiles, 148); each CTA loops over tiles
// (removes wave-quantization tail: 384 tiles / 148 SMs was 3 waves, now 2.59).
// round_out: fp16 output with cols<1024 scaled by QSCALE (Q); else fp32 out.
// ---------------------------------------------------------------------------
#define BM 128
#define BN 256
#define BK 64
#define HSTR 72                          // halves per row (64 + 8 pad)
#define WSTR 36                          // 32-bit words per row
#define A_TILE_H (BM * HSTR)             // 9216 halves
#define B_TILE_H (BN * HSTR)             // 18432 halves
#define STAGE_H  (A_TILE_H + B_TILE_H)   // 27648 halves
#define NSTAGE 3
#define GSMEM (NSTAGE * STAGE_H * 2)     // 165888 bytes

__global__ __launch_bounds__(256) void gemm_f16(
    const __half* __restrict__ A, const __half* __restrict__ Bw,
    void* __restrict__ Cv, int M, int N, int K, int round_out)
{
    extern __shared__ __half smh[];
    const int tid = threadIdx.x;
    const int wid = tid >> 5, lane = tid & 31;
    const int g = lane >> 2, tg = lane & 3;
    const int wm = (wid & 1) * 64, wn = (wid >> 1) * 64;

    const int tilesX = N / BN;
    const int nTiles = tilesX * (M / BM);
    const int KT = K / BK;

    for (int t = blockIdx.x; t < nTiles; t += gridDim.x) {
        const int m0 = (t / tilesX) * BM;
        const int n0 = (t % tilesX) * BN;

        __syncthreads();   // previous tile's readers done before stage reuse

        float acc[4][8][4];
#pragma unroll
        for (int mi = 0; mi < 4; mi++)
#pragma unroll
            for (int ni = 0; ni < 8; ni++)
#pragma unroll
                for (int j = 0; j < 4; j++) acc[mi][ni][j] = 0.f;

        auto load_stage = [&](int kt) {
            __half* base = smh + (kt % NSTAGE) * STAGE_H;
            const __half* Ag = A + (size_t)m0 * K + kt * BK;
            const __half* Bg = Bw + (size_t)n0 * K + kt * BK;
#pragma unroll
            for (int i = 0; i < 4; i++) {        // A: 1024 chunks of 16B
                int c = tid + i * 256;
                int row = c >> 3, col = c & 7;
                cp16(smem_u32(base + row * HSTR + col * 8),
                     Ag + (size_t)row * K + col * 8);
            }
            __half* bb = base + A_TILE_H;
#pragma unroll
            for (int i = 0; i < 8; i++) {        // B: 2048 chunks
                int c = tid + i * 256;
                int row = c >> 3, col = c & 7;
                cp16(smem_u32(bb + row * HSTR + col * 8),
                     Bg + (size_t)row * K + col * 8);
            }
        };

        load_stage(0); CP_COMMIT();
        load_stage(1); CP_COMMIT();

        for (int kt = 0; kt < KT; kt++) {
            CP_WAIT1();            // stage kt resident
            __syncthreads();       // all warps finished stage kt-1
            if (kt + 2 < KT) load_stage(kt + 2);
            CP_COMMIT();           // keep group counts aligned

            const uint32_t* As32 = reinterpret_cast<const uint32_t*>(
                smh + (kt % NSTAGE) * STAGE_H);
            const uint32_t* Bs32 = As32 + A_TILE_H / 2;

#pragma unroll
            for (int kk = 0; kk < 4; kk++) {     // 4 k16 steps per tile
                const int k0w = kk * 8;
                uint32_t af[4][4], bf[8][2];
#pragma unroll
                for (int mi = 0; mi < 4; mi++) {
                    int r0 = wm + mi * 16 + g;
                    af[mi][0] = As32[r0 * WSTR + k0w + tg];
                    af[mi][1] = As32[(r0 + 8) * WSTR + k0w + tg];
                    af[mi][2] = As32[r0 * WSTR + k0w + tg + 4];
                    af[mi][3] = As32[(r0 + 8) * WSTR + k0w + tg + 4];
                }
#pragma unroll
                for (int ni = 0; ni < 8; ni++) {
                    int rn = wn + ni * 8 + g;
                    bf[ni][0] = Bs32[rn * WSTR + k0w + tg];
                    bf[ni][1] = Bs32[rn * WSTR + k0w + tg + 4];
                }
#pragma unroll
                for (int mi = 0; mi < 4; mi++)
#pragma unroll
                    for (int ni = 0; ni < 8; ni++)
                        mma_f16(acc[mi][ni], af[mi], bf[ni]);
            }
        }

        if (round_out) {
            __half* Ch = (__half*)Cv;
#pragma unroll
            for (int mi = 0; mi < 4; mi++) {
                int r0 = m0 + wm + mi * 16 + g;
#pragma unroll
                for (int ni = 0; ni < 8; ni++) {
                    int cc = n0 + wn + ni * 8 + 2 * tg;
                    float sc = (cc < CMODEL) ? QSCALE : 1.f;   // Q: 1/8*log2(e)
                    *reinterpret_cast<__half2*>(&Ch[(size_t)r0 * N + cc]) =
                        __floats2half2_rn(acc[mi][ni][0] * sc, acc[mi][ni][1] * sc);
                    *reinterpret_cast<__half2*>(&Ch[(size_t)(r0 + 8) * N + cc]) =
                        __floats2half2_rn(acc[mi][ni][2] * sc, acc[mi][ni][3] * sc);
                }
            }
        } else {
            float* Cf = (float*)Cv;
#pragma unroll
            for (int mi = 0; mi < 4; mi++) {
                int r0 = m0 + wm + mi * 16 + g;
#pragma unroll
                for (int ni = 0; ni < 8; ni++) {
                    int cc = n0 + wn + ni * 8 + 2 * tg;
                    *reinterpret_cast<float2*>(&Cf[(size_t)r0 * N + cc]) =
                        make_float2(acc[mi][ni][0], acc[mi][ni][1]);
                    *reinterpret_cast<float2*>(&Cf[(size_t)(r0 + 8) * N + cc]) =
                        make_float2(acc[mi][ni][2], acc[mi][ni][3]);
                }
            }
        }
    }
}

// ---------------------------------------------------------------------------
// fp16 tensor-core flash attention (causal), exp2 softmax, register-resident
// P (R13 winner, unchanged).
// CTA: 128 q-rows of one (b,h), 8 warps x 16 rows, key tiles of 64
// double-buffered. V via ldmatrix.trans. smem 54KB -> 2 CTAs/SM.
// ---------------------------------------------------------------------------
#define BR 128
#define BC 64
#define AQSTR 72                              // halves (36 words)
#define OFF_Q 0
#define OFF_K (BR * AQSTR)                    // 9216 halves
#define OFF_V (OFF_K + 2 * BC * AQSTR)        // 18432
#define ATTN_SMEM_H (OFF_V + 2 * BC * AQSTR)  // 27648 halves
#define ATTN_SMEM (ATTN_SMEM_H * 2)           // 55296 bytes

__global__ __launch_bounds__(256, 2) void attn_f16_kernel()
{
    extern __shared__ __half smh[];
    const int tid = threadIdx.x;
    const int wid = tid >> 5, lane = tid & 31;
    const int g = lane >> 2, tg = lane & 3;
    const int ib = (int)gridDim.x - 1 - (int)blockIdx.x;   // big tiles first
    const int h = blockIdx.y, b = blockIdx.z;
    const int ibase = ib * BR;
    const int hoff = h * DHEAD;
    const int wm = wid * 16;

    // ---- async load Q tile + KV tile 0 ----
    {
        const __half* Qg = g_qkvh + (size_t)(b * T_ + ibase) * F3 + hoff;
        for (int i = tid; i < BR * 8; i += 256) {
            int row = i >> 3, c = i & 7;
            cp16(smem_u32(smh + OFF_Q + row * AQSTR + c * 8),
                 Qg + (size_t)row * F3 + c * 8);
        }
    }
    auto load_kv = [&](int jb) {
        int buf = jb & 1;
        const __half* Kg = g_qkvh + (size_t)(b * T_ + jb * BC) * F3 + CMODEL + hoff;
        const __half* Vg = Kg + CMODEL;
        __half* Kb = smh + OFF_K + buf * BC * AQSTR;
        __half* Vb = smh + OFF_V + buf * BC * AQSTR;
        for (int i = tid; i < BC * 8; i += 256) {
            int row = i >> 3, c = i & 7;
            cp16(smem_u32(Kb + row * AQSTR + c * 8), Kg + (size_t)row * F3 + c * 8);
            cp16(smem_u32(Vb + row * AQSTR + c * 8), Vg + (size_t)row * F3 + c * 8);
        }
    };
    load_kv(0);
    CP_COMMIT();

    const int NT = 2 * ib + 2;

    float m0 = -1e30f, m1 = -1e30f, l0 = 0.f, l1 = 0.f;
    float o[8][4];
#pragma unroll
    for (int ni = 0; ni < 8; ni++)
#pragma unroll
        for (int j = 0; j < 4; j++) o[ni][j] = 0.f;

    // Q fragments register-resident
    CP_WAIT0();
    __syncthreads();
    uint32_t qf[4][4];
    {
        const uint32_t* Qs32 = reinterpret_cast<const uint32_t*>(smh + OFF_Q);
#pragma unroll
        for (int kk = 0; kk < 4; kk++) {
            qf[kk][0] = Qs32[(wm + g) * WSTR + kk * 8 + tg];
            qf[kk][1] = Qs32[(wm + g + 8) * WSTR + kk * 8 + tg];
            qf[kk][2] = Qs32[(wm + g) * WSTR + kk * 8 + tg + 4];
            qf[kk][3] = Qs32[(wm + g + 8) * WSTR + kk * 8 + tg + 4];
        }
    }

    for (int jb = 0; jb < NT; jb++) {
        if (jb > 0) {
            CP_WAIT0();        // KV jb resident
            __syncthreads();   // all warps done with buffer (jb-1)&1
        }
        if (jb + 1 < NT) {
            load_kv(jb + 1);
            CP_COMMIT();
        }

        const int jbase = jb * BC;
        const bool skip = (jbase > ibase + wm + 15);
        if (!skip) {
            const __half* Vb = smh + OFF_V + (jb & 1) * BC * AQSTR;
            const uint32_t* Kb32 = reinterpret_cast<const uint32_t*>(
                smh + OFF_K + (jb & 1) * BC * AQSTR);

            // ---- S = Q K^T (scores already in log2 domain) ----
            float s[8][4];
#pragma unroll
            for (int ni = 0; ni < 8; ni++)
#pragma unroll
                for (int j = 0; j < 4; j++) s[ni][j] = 0.f;
#pragma unroll
            for (int kk = 0; kk < 4; kk++) {
                const int k0w = kk * 8;
#pragma unroll
                for (int ni = 0; ni < 8; ni++) {
                    uint32_t bfr[2];
                    bfr[0] = Kb32[(ni * 8 + g) * WSTR + k0w + tg];
                    bfr[1] = Kb32[(ni * 8 + g) * WSTR + k0w + tg + 4];
                    mma_f16(s[ni], qf[kk], bfr);
                }
            }

            // ---- causal mask ----
            const int qr0 = ibase + wm + g;
            const int qr1 = qr0 + 8;
            const bool full = (jbase + BC - 1 <= ibase + wm);
            if (!full) {
#pragma unroll
                for (int ni = 0; ni < 8; ni++) {
                    int kc = jbase + ni * 8 + 2 * tg;
                    if (kc > qr0)     s[ni][0] = -1e30f;
                    if (kc + 1 > qr0) s[ni][1] = -1e30f;
                    if (kc > qr1)     s[ni][2] = -1e30f;
                    if (kc + 1 > qr1) s[ni][3] = -1e30f;
                }
            }

            // ---- online softmax (exp2 domain), P packed in registers ----
            float rm0 = -1e30f, rm1 = -1e30f;
#pragma unroll
            for (int ni = 0; ni < 8; ni++) {
                rm0 = fmaxf(rm0, fmaxf(s[ni][0], s[ni][1]));
                rm1 = fmaxf(rm1, fmaxf(s[ni][2], s[ni][3]));
            }
            rm0 = fmaxf(rm0, __shfl_xor_sync(0xffffffffu, rm0, 1));
            rm0 = fmaxf(rm0, __shfl_xor_sync(0xffffffffu, rm0, 2));
            rm1 = fmaxf(rm1, __shfl_xor_sync(0xffffffffu, rm1, 1));
            rm1 = fmaxf(rm1, __shfl_xor_sync(0xffffffffu, rm1, 2));
            float mn0 = fmaxf(m0, rm0), mn1 = fmaxf(m1, rm1);
            float c0 = fexp2(m0 - mn0), c1 = fexp2(m1 - mn1);
            m0 = mn0; m1 = mn1;

            uint32_t ph[8][2];   // [ni][0] rows g (p0,p1); [1] rows g+8
            float ls0 = 0.f, ls1 = 0.f;
#pragma unroll
            for (int ni = 0; ni < 8; ni++) {
                float p0 = fexp2(s[ni][0] - mn0);
                float p1 = fexp2(s[ni][1] - mn0);
                float p2 = fexp2(s[ni][2] - mn1);
                float p3 = fexp2(s[ni][3] - mn1);
                ls0 += p0 + p1; ls1 += p2 + p3;
                ph[ni][0] = h2u(__floats2half2_rn(p0, p1));
                ph[ni][1] = h2u(__floats2half2_rn(p2, p3));
            }
            ls0 += __shfl_xor_sync(0xffffffffu, ls0, 1);
            ls0 += __shfl_xor_sync(0xffffffffu, ls0, 2);
            ls1 += __shfl_xor_sync(0xffffffffu, ls1, 1);
            ls1 += __shfl_xor_sync(0xffffffffu, ls1, 2);
            l0 = l0 * c0 + ls0;
            l1 = l1 * c1 + ls1;
#pragma unroll
            for (int ni = 0; ni < 8; ni++) {
                o[ni][0] *= c0; o[ni][1] *= c0;
                o[ni][2] *= c1; o[ni][3] *= c1;
            }

            // ---- O += P V (P A-frags direct from registers) ----
#pragma unroll
            for (int kk = 0; kk < 4; kk++) {       // key blocks of 16
                const int k0 = kk * 16;
                uint32_t ap[4] = { ph[2 * kk][0], ph[2 * kk][1],
                                   ph[2 * kk + 1][0], ph[2 * kk + 1][1] };
#pragma unroll
                for (int np = 0; np < 4; np++) {   // d-blocks of 16 (2 ni each)
                    uint32_t vr[4];
                    const __half* vaddr = (lane < 16)
                        ? &Vb[(k0 + lane) * AQSTR + np * 16]
                        : &Vb[(k0 + lane - 16) * AQSTR + np * 16 + 8];
                    ldsm_x4_trans(vr, smem_u32(vaddr));
                    mma_f16(o[2 * np],     ap, vr);
                    mma_f16(o[2 * np + 1], ap, vr + 2);
                }
            }
        }
    }

    // ---- epilogue: O / l -> fp16 g_attnh ----
    const float inv0 = 1.f / l0, inv1 = 1.f / l1;
    __half* O0 = g_attnh + (size_t)(b * T_ + ibase + wm + g) * CMODEL + hoff;
    __half* O1 = O0 + 8 * CMODEL;
#pragma unroll
    for (int ni = 0; ni < 8; ni++) {
        int cc = ni * 8 + 2 * tg;
        *reinterpret_cast<__half2*>(O0 + cc) =
            __floats2half2_rn(o[ni][0] * inv0, o[ni][1] * inv0);
        *reinterpret_cast<__half2*>(O1 + cc) =
            __floats2half2_rn(o[ni][2] * inv1, o[ni][3] * inv1);
    }
}

// ---------------------------------------------------------------------------
// Launch
// ---------------------------------------------------------------------------
extern "C" void kernel_launch(void* const* d_in, const int* in_sizes, int n_in,
                              void* d_out, int out_size)
{
    const float* x    = (const float*)d_in[0];
    const float* Wqkv = (const float*)d_in[1];
    const float* Wout = (const float*)d_in[2];
    float* out = (float*)d_out;

    __half *qkvh, *attnh, *xh, *wqh, *woh;
    cudaGetSymbolAddress((void**)&qkvh, g_qkvh);
    cudaGetSymbolAddress((void**)&attnh, g_attnh);
    cudaGetSymbolAddress((void**)&xh, g_xh);
    cudaGetSymbolAddress((void**)&wqh, g_wqh);
    cudaGetSymbolAddress((void**)&woh, g_woh);

    cudaFuncSetAttribute(gemm_f16,
                         cudaFuncAttributeMaxDynamicSharedMemorySize, GSMEM);
    cudaFuncSetAttribute(attn_f16_kernel,
                         cudaFuncAttributeMaxDynamicSharedMemorySize, ATTN_SMEM);

    // 0) pre-round inputs to fp16
    round_f16_kernel<<<1024, 256>>>(
        (const float4*)x,    (uint2*)xh,  (NTOK * CMODEL) / 4,
        (const float4*)Wqkv, (uint2*)wqh, (F3 * CMODEL) / 4,
        (const float4*)Wout, (uint2*)woh, (CMODEL * CMODEL) / 4);

    // 1) qkv = x @ Wqkv^T  (persistent grid: 384 tiles on 148 CTAs)
    {
        int tiles = (F3 / BN) * (NTOK / BM);
        int grid = tiles < NSM ? tiles : NSM;
        gemm_f16<<<grid, 256, GSMEM>>>(xh, wqh, qkvh, NTOK, F3, CMODEL, 1);
    }

    // 2) causal flash attention (fp16 tensor cores, register-resident P)
    attn_f16_kernel<<<dim3(T_ / BR, NHEADS, B_), 256, ATTN_SMEM>>>();

    // 3) out = attn @ Wout^T  (128 tiles -> one wave, same persistent code)
    {
        int tiles = (CMODEL / BN) * (NTOK / BM);
        int grid = tiles < NSM ? tiles : NSM;
        gemm_f16<<<grid, 256, GSMEM>>>(attnh, woh, out, NTOK, CMODEL, CMODEL, 0);
    }
}

// round 15
// speedup vs baseline: 1.0351x; 1.0351x over previous
#include <cuda_runtime.h>
#include <cuda_fp16.h>
#include <cstdint>
#include <math.h>

// Problem constants
#define B_     2
#define T_     2048
#define CMODEL 1024
#define NHEADS 16
#define DHEAD  64
#define NTOK   (B_ * T_)          // 4096
#define F3     (3 * CMODEL)       // 3072

// Scratch (fp16)
__device__ __align__(256) __half g_qkvh[NTOK * F3];       // GEMM1 out, q pre-scaled
__device__ __align__(256) __half g_attnh[NTOK * CMODEL];  // attention out
__device__ __align__(256) __half g_xh[NTOK * CMODEL];
__device__ __align__(256) __half g_wqh[F3 * CMODEL];
__device__ __align__(256) __half g_woh[CMODEL * CMODEL];

// Q pre-scale: (1/sqrt(64)) * log2(e)  -> scores land in log2 domain
#define QSCALE 0.18033688011112042f

// ---------------------------------------------------------------------------
// Helpers
// ---------------------------------------------------------------------------
__device__ __forceinline__ uint32_t smem_u32(const void* p) {
    uint32_t a;
    asm("{ .reg .u64 t; cvta.to.shared.u64 t, %1; cvt.u32.u64 %0, t; }"
        : "=r"(a) : "l"(p));
    return a;
}
__device__ __forceinline__ void cp16(uint32_t dst, const void* src) {
    asm volatile("cp.async.cg.shared.global [%0], [%1], 16;" :: "r"(dst), "l"(src));
}
#define CP_COMMIT() asm volatile("cp.async.commit_group;" ::: "memory")
#define CP_WAIT0()  asm volatile("cp.async.wait_group 0;" ::: "memory")
#define CP_WAIT1()  asm volatile("cp.async.wait_group 1;" ::: "memory")

__device__ __forceinline__ void mma_f16(float* c, const uint32_t* a, const uint32_t* b) {
    asm volatile(
        "mma.sync.aligned.m16n8k16.row.col.f32.f16.f16.f32 "
        "{%0,%1,%2,%3}, {%4,%5,%6,%7}, {%8,%9}, {%0,%1,%2,%3};"
        : "+f"(c[0]), "+f"(c[1]), "+f"(c[2]), "+f"(c[3])
        : "r"(a[0]), "r"(a[1]), "r"(a[2]), "r"(a[3]), "r"(b[0]), "r"(b[1]));
}
__device__ __forceinline__ void ldsm_x4_trans(uint32_t* r, uint32_t addr) {
    asm volatile("ldmatrix.sync.aligned.m8n8.x4.trans.shared.b16 {%0,%1,%2,%3}, [%4];"
                 : "=r"(r[0]), "=r"(r[1]), "=r"(r[2]), "=r"(r[3]) : "r"(addr));
}
__device__ __forceinline__ uint32_t h2u(__half2 h) {
    uint32_t u; *reinterpret_cast<__half2*>(&u) = h; return u;
}
__device__ __forceinline__ float fexp2(float x) {
    float r;
    asm("ex2.approx.f32 %0, %1;" : "=f"(r) : "f"(x));
    return r;
}

// ---------------------------------------------------------------------------
// Pre-round pass: fp32 inputs -> fp16 copies
// ---------------------------------------------------------------------------
__global__ __launch_bounds__(256) void round_f16_kernel(
    const float4* __restrict__ a, uint2* __restrict__ da, int na4,
    const float4* __restrict__ b, uint2* __restrict__ db, int nb4,
    const float4* __restrict__ c, uint2* __restrict__ dc, int nc4)
{
    int total = na4 + nb4 + nc4;
    for (int i = blockIdx.x * blockDim.x + threadIdx.x; i < total;
         i += gridDim.x * blockDim.x) {
        const float4* s; uint2* d; int j;
        if (i < na4)            { s = a; d = da; j = i; }
        else if (i < na4 + nb4) { s = b; d = db; j = i - na4; }
        else                    { s = c; d = dc; j = i - na4 - nb4; }
        float4 v = s[j];
        d[j] = make_uint2(h2u(__floats2half2_rn(v.x, v.y)),
                          h2u(__floats2half2_rn(v.z, v.w)));
    }
}

// ---------------------------------------------------------------------------
// fp16 GEMM: C[M,N] = A[M,K] * B[N,K]^T, fp32 accum. Templated on CTA-N and
// warp count; warp tile FIXED at 64x64 (the proven shape).
//   TBN=256, 8 warps : R8/R13 config (GEMM3)
//   TBN=384, 12 warps: 3 warps/SMSP, same per-warp stream (GEMM1)
// BK=64, 3-stage cp.async, scalar-LDS fragments.
// round_out: fp16 output with cols<1024 scaled by QSCALE (Q); else fp32 out.
// ---------------------------------------------------------------------------
#define BM 128
#define BK 64
#define HSTR 72                          // halves per row (64 + 8 pad)
#define WSTR 36                          // 32-bit words per row
#define A_TILE_H (BM * HSTR)             // 9216 halves
#define NSTAGE 3

template<int TBN, int TTHREADS>
__global__ __launch_bounds__(TTHREADS) void gemm_f16(
    const __half* __restrict__ A, const __half* __restrict__ Bw,
    void* __restrict__ Cv, int M, int N, int K, int round_out)
{
    constexpr int B_TILE_H = TBN * HSTR;
    constexpr int STAGE_H = A_TILE_H + B_TILE_H;

    extern __shared__ __half smh[];
    const int tid = threadIdx.x;
    const int wid = tid >> 5, lane = tid & 31;
    const int g = lane >> 2, tg = lane & 3;
    const int m0 = blockIdx.y * BM, n0 = blockIdx.x * TBN;
    const int wm = (wid & 1) * 64, wn = (wid >> 1) * 64;

    float acc[4][8][4];
#pragma unroll
    for (int mi = 0; mi < 4; mi++)
#pragma unroll
        for (int ni = 0; ni < 8; ni++)
#pragma unroll
            for (int j = 0; j < 4; j++) acc[mi][ni][j] = 0.f;

    const int KT = K / BK;

    auto load_stage = [&](int kt) {
        __half* base = smh + (kt % NSTAGE) * STAGE_H;
        const __half* Ag = A + (size_t)m0 * K + kt * BK;
        const __half* Bg = Bw + (size_t)n0 * K + kt * BK;
        for (int c = tid; c < BM * 8; c += TTHREADS) {      // A: 1024 chunks
            int row = c >> 3, col = c & 7;
            cp16(smem_u32(base + row * HSTR + col * 8),
                 Ag + (size_t)row * K + col * 8);
        }
        __half* bb = base + A_TILE_H;
        for (int c = tid; c < TBN * 8; c += TTHREADS) {     // B chunks
            int row = c >> 3, col = c & 7;
            cp16(smem_u32(bb + row * HSTR + col * 8),
                 Bg + (size_t)row * K + col * 8);
        }
    };

    load_stage(0); CP_COMMIT();
    load_stage(1); CP_COMMIT();

    for (int kt = 0; kt < KT; kt++) {
        CP_WAIT1();            // stage kt resident
        __syncthreads();       // all warps finished stage kt-1
        if (kt + 2 < KT) load_stage(kt + 2);
        CP_COMMIT();           // keep group counts aligned

        const uint32_t* As32 = reinterpret_cast<const uint32_t*>(
            smh + (kt % NSTAGE) * STAGE_H);
        const uint32_t* Bs32 = As32 + A_TILE_H / 2;

#pragma unroll
        for (int kk = 0; kk < 4; kk++) {     // 4 k16 steps per tile
            const int k0w = kk * 8;
            uint32_t af[4][4], bf[8][2];
#pragma unroll
            for (int mi = 0; mi < 4; mi++) {
                int r0 = wm + mi * 16 + g;
                af[mi][0] = As32[r0 * WSTR + k0w + tg];
                af[mi][1] = As32[(r0 + 8) * WSTR + k0w + tg];
                af[mi][2] = As32[r0 * WSTR + k0w + tg + 4];
                af[mi][3] = As32[(r0 + 8) * WSTR + k0w + tg + 4];
            }
#pragma unroll
            for (int ni = 0; ni < 8; ni++) {
                int rn = wn + ni * 8 + g;
                bf[ni][0] = Bs32[rn * WSTR + k0w + tg];
                bf[ni][1] = Bs32[rn * WSTR + k0w + tg + 4];
            }
#pragma unroll
            for (int mi = 0; mi < 4; mi++)
#pragma unroll
                for (int ni = 0; ni < 8; ni++)
                    mma_f16(acc[mi][ni], af[mi], bf[ni]);
        }
    }

    if (round_out) {
        __half* Ch = (__half*)Cv;
#pragma unroll
        for (int mi = 0; mi < 4; mi++) {
            int r0 = m0 + wm + mi * 16 + g;
#pragma unroll
            for (int ni = 0; ni < 8; ni++) {
                int cc = n0 + wn + ni * 8 + 2 * tg;
                float sc = (cc < CMODEL) ? QSCALE : 1.f;   // Q: 1/8 * log2(e)
                *reinterpret_cast<__half2*>(&Ch[(size_t)r0 * N + cc]) =
                    __floats2half2_rn(acc[mi][ni][0] * sc, acc[mi][ni][1] * sc);
                *reinterpret_cast<__half2*>(&Ch[(size_t)(r0 + 8) * N + cc]) =
                    __floats2half2_rn(acc[mi][ni][2] * sc, acc[mi][ni][3] * sc);
            }
        }
    } else {
        float* Cf = (float*)Cv;
#pragma unroll
        for (int mi = 0; mi < 4; mi++) {
            int r0 = m0 + wm + mi * 16 + g;
#pragma unroll
            for (int ni = 0; ni < 8; ni++) {
                int cc = n0 + wn + ni * 8 + 2 * tg;
                *reinterpret_cast<float2*>(&Cf[(size_t)r0 * N + cc]) =
                    make_float2(acc[mi][ni][0], acc[mi][ni][1]);
                *reinterpret_cast<float2*>(&Cf[(size_t)(r0 + 8) * N + cc]) =
                    make_float2(acc[mi][ni][2], acc[mi][ni][3]);
            }
        }
    }
}

#define GSMEM_256 (NSTAGE * (A_TILE_H + 256 * HSTR) * 2)   // 165888 bytes
#define GSMEM_384 (NSTAGE * (A_TILE_H + 384 * HSTR) * 2)   // 221184 bytes

// ---------------------------------------------------------------------------
// fp16 tensor-core flash attention (causal), exp2 softmax, register-resident
// P (R13 winner, unchanged).
// CTA: 128 q-rows of one (b,h), 8 warps x 16 rows, key tiles of 64
// double-buffered. V via ldmatrix.trans. smem 54KB -> 2 CTAs/SM.
// ---------------------------------------------------------------------------
#define BR 128
#define BC 64
#define AQSTR 72                              // halves (36 words)
#define OFF_Q 0
#define OFF_K (BR * AQSTR)                    // 9216 halves
#define OFF_V (OFF_K + 2 * BC * AQSTR)        // 18432
#define ATTN_SMEM_H (OFF_V + 2 * BC * AQSTR)  // 27648 halves
#define ATTN_SMEM (ATTN_SMEM_H * 2)           // 55296 bytes

__global__ __launch_bounds__(256, 2) void attn_f16_kernel()
{
    extern __shared__ __half smh[];
    const int tid = threadIdx.x;
    const int wid = tid >> 5, lane = tid & 31;
    const int g = lane >> 2, tg = lane & 3;
    const int ib = (int)gridDim.x - 1 - (int)blockIdx.x;   // big tiles first
    const int h = blockIdx.y, b = blockIdx.z;
    const int ibase = ib * BR;
    const int hoff = h * DHEAD;
    const int wm = wid * 16;

    // ---- async load Q tile + KV tile 0 ----
    {
        const __half* Qg = g_qkvh + (size_t)(b * T_ + ibase) * F3 + hoff;
        for (int i = tid; i < BR * 8; i += 256) {
            int row = i >> 3, c = i & 7;
            cp16(smem_u32(smh + OFF_Q + row * AQSTR + c * 8),
                 Qg + (size_t)row * F3 + c * 8);
        }
    }
    auto load_kv = [&](int jb) {
        int buf = jb & 1;
        const __half* Kg = g_qkvh + (size_t)(b * T_ + jb * BC) * F3 + CMODEL + hoff;
        const __half* Vg = Kg + CMODEL;
        __half* Kb = smh + OFF_K + buf * BC * AQSTR;
        __half* Vb = smh + OFF_V + buf * BC * AQSTR;
        for (int i = tid; i < BC * 8; i += 256) {
            int row = i >> 3, c = i & 7;
            cp16(smem_u32(Kb + row * AQSTR + c * 8), Kg + (size_t)row * F3 + c * 8);
            cp16(smem_u32(Vb + row * AQSTR + c * 8), Vg + (size_t)row * F3 + c * 8);
        }
    };
    load_kv(0);
    CP_COMMIT();

    const int NT = 2 * ib + 2;

    float m0 = -1e30f, m1 = -1e30f, l0 = 0.f, l1 = 0.f;
    float o[8][4];
#pragma unroll
    for (int ni = 0; ni < 8; ni++)
#pragma unroll
        for (int j = 0; j < 4; j++) o[ni][j] = 0.f;

    // Q fragments register-resident
    CP_WAIT0();
    __syncthreads();
    uint32_t qf[4][4];
    {
        const uint32_t* Qs32 = reinterpret_cast<const uint32_t*>(smh + OFF_Q);
#pragma unroll
        for (int kk = 0; kk < 4; kk++) {
            qf[kk][0] = Qs32[(wm + g) * WSTR + kk * 8 + tg];
            qf[kk][1] = Qs32[(wm + g + 8) * WSTR + kk * 8 + tg];
            qf[kk][2] = Qs32[(wm + g) * WSTR + kk * 8 + tg + 4];
            qf[kk][3] = Qs32[(wm + g + 8) * WSTR + kk * 8 + tg + 4];
        }
    }

    for (int jb = 0; jb < NT; jb++) {
        if (jb > 0) {
            CP_WAIT0();        // KV jb resident
            __syncthreads();   // all warps done with buffer (jb-1)&1
        }
        if (jb + 1 < NT) {
            load_kv(jb + 1);
            CP_COMMIT();
        }

        const int jbase = jb * BC;
        const bool skip = (jbase > ibase + wm + 15);
        if (!skip) {
            const __half* Vb = smh + OFF_V + (jb & 1) * BC * AQSTR;
            const uint32_t* Kb32 = reinterpret_cast<const uint32_t*>(
                smh + OFF_K + (jb & 1) * BC * AQSTR);

            // ---- S = Q K^T (scores already in log2 domain) ----
            float s[8][4];
#pragma unroll
            for (int ni = 0; ni < 8; ni++)
#pragma unroll
                for (int j = 0; j < 4; j++) s[ni][j] = 0.f;
#pragma unroll
            for (int kk = 0; kk < 4; kk++) {
                const int k0w = kk * 8;
#pragma unroll
                for (int ni = 0; ni < 8; ni++) {
                    uint32_t bfr[2];
                    bfr[0] = Kb32[(ni * 8 + g) * WSTR + k0w + tg];
                    bfr[1] = Kb32[(ni * 8 + g) * WSTR + k0w + tg + 4];
                    mma_f16(s[ni], qf[kk], bfr);
                }
            }

            // ---- causal mask ----
            const int qr0 = ibase + wm + g;
            const int qr1 = qr0 + 8;
            const bool full = (jbase + BC - 1 <= ibase + wm);
            if (!full) {
#pragma unroll
                for (int ni = 0; ni < 8; ni++) {
                    int kc = jbase + ni * 8 + 2 * tg;
                    if (kc > qr0)     s[ni][0] = -1e30f;
                    if (kc + 1 > qr0) s[ni][1] = -1e30f;
                    if (kc > qr1)     s[ni][2] = -1e30f;
                    if (kc + 1 > qr1) s[ni][3] = -1e30f;
                }
            }

            // ---- online softmax (exp2 domain), P packed in registers ----
            float rm0 = -1e30f, rm1 = -1e30f;
#pragma unroll
            for (int ni = 0; ni < 8; ni++) {
                rm0 = fmaxf(rm0, fmaxf(s[ni][0], s[ni][1]));
                rm1 = fmaxf(rm1, fmaxf(s[ni][2], s[ni][3]));
            }
            rm0 = fmaxf(rm0, __shfl_xor_sync(0xffffffffu, rm0, 1));
            rm0 = fmaxf(rm0, __shfl_xor_sync(0xffffffffu, rm0, 2));
            rm1 = fmaxf(rm1, __shfl_xor_sync(0xffffffffu, rm1, 1));
            rm1 = fmaxf(rm1, __shfl_xor_sync(0xffffffffu, rm1, 2));
            float mn0 = fmaxf(m0, rm0), mn1 = fmaxf(m1, rm1);
            float c0 = fexp2(m0 - mn0), c1 = fexp2(m1 - mn1);
            m0 = mn0; m1 = mn1;

            uint32_t ph[8][2];   // [ni][0] rows g (p0,p1); [1] rows g+8
            float ls0 = 0.f, ls1 = 0.f;
#pragma unroll
            for (int ni = 0; ni < 8; ni++) {
                float p0 = fexp2(s[ni][0] - mn0);
                float p1 = fexp2(s[ni][1] - mn0);
                float p2 = fexp2(s[ni][2] - mn1);
                float p3 = fexp2(s[ni][3] - mn1);
                ls0 += p0 + p1; ls1 += p2 + p3;
                ph[ni][0] = h2u(__floats2half2_rn(p0, p1));
                ph[ni][1] = h2u(__floats2half2_rn(p2, p3));
            }
            ls0 += __shfl_xor_sync(0xffffffffu, ls0, 1);
            ls0 += __shfl_xor_sync(0xffffffffu, ls0, 2);
            ls1 += __shfl_xor_sync(0xffffffffu, ls1, 1);
            ls1 += __shfl_xor_sync(0xffffffffu, ls1, 2);
            l0 = l0 * c0 + ls0;
            l1 = l1 * c1 + ls1;
#pragma unroll
            for (int ni = 0; ni < 8; ni++) {
                o[ni][0] *= c0; o[ni][1] *= c0;
                o[ni][2] *= c1; o[ni][3] *= c1;
            }

            // ---- O += P V (P A-frags direct from registers) ----
#pragma unroll
            for (int kk = 0; kk < 4; kk++) {       // key blocks of 16
                const int k0 = kk * 16;
                uint32_t ap[4] = { ph[2 * kk][0], ph[2 * kk][1],
                                   ph[2 * kk + 1][0], ph[2 * kk + 1][1] };
#pragma unroll
                for (int np = 0; np < 4; np++) {   // d-blocks of 16 (2 ni each)
                    uint32_t vr[4];
                    const __half* vaddr = (lane < 16)
                        ? &Vb[(k0 + lane) * AQSTR + np * 16]
                        : &Vb[(k0 + lane - 16) * AQSTR + np * 16 + 8];
                    ldsm_x4_trans(vr, smem_u32(vaddr));
                    mma_f16(o[2 * np],     ap, vr);
                    mma_f16(o[2 * np + 1], ap, vr + 2);
                }
            }
        }
    }

    // ---- epilogue: O / l -> fp16 g_attnh ----
    const float inv0 = 1.f / l0, inv1 = 1.f / l1;
    __half* O0 = g_attnh + (size_t)(b * T_ + ibase + wm + g) * CMODEL + hoff;
    __half* O1 = O0 + 8 * CMODEL;
#pragma unroll
    for (int ni = 0; ni < 8; ni++) {
        int cc = ni * 8 + 2 * tg;
        *reinterpret_cast<__half2*>(O0 + cc) =
            __floats2half2_rn(o[ni][0] * inv0, o[ni][1] * inv0);
        *reinterpret_cast<__half2*>(O1 + cc) =
            __floats2half2_rn(o[ni][2] * inv1, o[ni][3] * inv1);
    }
}

// ---------------------------------------------------------------------------
// Launch
// ---------------------------------------------------------------------------
extern "C" void kernel_launch(void* const* d_in, const int* in_sizes, int n_in,
                              void* d_out, int out_size)
{
    const float* x    = (const float*)d_in[0];
    const float* Wqkv = (const float*)d_in[1];
    const float* Wout = (const float*)d_in[2];
    float* out = (float*)d_out;

    __half *qkvh, *attnh, *xh, *wqh, *woh;
    cudaGetSymbolAddress((void**)&qkvh, g_qkvh);
    cudaGetSymbolAddress((void**)&attnh, g_attnh);
    cudaGetSymbolAddress((void**)&xh, g_xh);
    cudaGetSymbolAddress((void**)&wqh, g_wqh);
    cudaGetSymbolAddress((void**)&woh, g_woh);

    cudaFuncSetAttribute(gemm_f16<384, 384>,
                         cudaFuncAttributeMaxDynamicSharedMemorySize, GSMEM_384);
    cudaFuncSetAttribute(gemm_f16<256, 256>,
                         cudaFuncAttributeMaxDynamicSharedMemorySize, GSMEM_256);
    cudaFuncSetAttribute(attn_f16_kernel,
                         cudaFuncAttributeMaxDynamicSharedMemorySize, ATTN_SMEM);

    // 0) pre-round inputs to fp16
    round_f16_kernel<<<1024, 256>>>(
        (const float4*)x,    (uint2*)xh,  (NTOK * CMODEL) / 4,
        (const float4*)Wqkv, (uint2*)wqh, (F3 * CMODEL) / 4,
        (const float4*)Wout, (uint2*)woh, (CMODEL * CMODEL) / 4);

    // 1) qkv = x @ Wqkv^T  (128x384 CTA, 12 warps = 3/SMSP, warp tile 64x64;
    //    256 tiles -> 2 waves instead of 3)
    gemm_f16<384, 384><<<dim3(F3 / 384, NTOK / BM), 384, GSMEM_384>>>(
        xh, wqh, qkvh, NTOK, F3, CMODEL, 1);

    // 2) causal flash attention (fp16 tensor cores, register-resident P)
    attn_f16_kernel<<<dim3(T_ / BR, NHEADS, B_), 256, ATTN_SMEM>>>();

    // 3) out = attn @ Wout^T  (proven 128x256 / 8-warp config)
    gemm_f16<256, 256><<<dim3(CMODEL / 256, NTOK / BM), 256, GSMEM_256>>>(
        attnh, woh, out, NTOK, CMODEL, CMODEL, 0);
}

// round 16
// speedup vs baseline: 1.0839x; 1.0471x over previous
#include <cuda_runtime.h>
#include <cuda_fp16.h>
#include <cstdint>
#include <math.h>

// Problem constants
#define B_     2
#define T_     2048
#define CMODEL 1024
#define NHEADS 16
#define DHEAD  64
#define NTOK   (B_ * T_)          // 4096
#define F3     (3 * CMODEL)       // 3072

// Scratch (fp16)
__device__ __align__(256) __half g_qkvh[NTOK * F3];       // GEMM1 out, q pre-scaled
__device__ __align__(256) __half g_attnh[NTOK * CMODEL];  // attention out
__device__ __align__(256) __half g_xh[NTOK * CMODEL];
__device__ __align__(256) __half g_wqh[F3 * CMODEL];
__device__ __align__(256) __half g_woh[CMODEL * CMODEL];

// Q pre-scale: (1/sqrt(64)) * log2(e)  -> scores land in log2 domain
#define QSCALE 0.18033688011112042f

// ---------------------------------------------------------------------------
// Helpers
// ---------------------------------------------------------------------------
__device__ __forceinline__ uint32_t smem_u32(const void* p) {
    uint32_t a;
    asm("{ .reg .u64 t; cvta.to.shared.u64 t, %1; cvt.u32.u64 %0, t; }"
        : "=r"(a) : "l"(p));
    return a;
}
__device__ __forceinline__ void cp16(uint32_t dst, const void* src) {
    asm volatile("cp.async.cg.shared.global [%0], [%1], 16;" :: "r"(dst), "l"(src));
}
#define CP_COMMIT() asm volatile("cp.async.commit_group;" ::: "memory")
#define CP_WAIT0()  asm volatile("cp.async.wait_group 0;" ::: "memory")
#define CP_WAIT1()  asm volatile("cp.async.wait_group 1;" ::: "memory")

__device__ __forceinline__ void mma_f16(float* c, const uint32_t* a, const uint32_t* b) {
    asm volatile(
        "mma.sync.aligned.m16n8k16.row.col.f32.f16.f16.f32 "
        "{%0,%1,%2,%3}, {%4,%5,%6,%7}, {%8,%9}, {%0,%1,%2,%3};"
        : "+f"(c[0]), "+f"(c[1]), "+f"(c[2]), "+f"(c[3])
        : "r"(a[0]), "r"(a[1]), "r"(a[2]), "r"(a[3]), "r"(b[0]), "r"(b[1]));
}
__device__ __forceinline__ void ldsm_x4_trans(uint32_t* r, uint32_t addr) {
    asm volatile("ldmatrix.sync.aligned.m8n8.x4.trans.shared.b16 {%0,%1,%2,%3}, [%4];"
                 : "=r"(r[0]), "=r"(r[1]), "=r"(r[2]), "=r"(r[3]) : "r"(addr));
}
__device__ __forceinline__ uint32_t h2u(__half2 h) {
    uint32_t u; *reinterpret_cast<__half2*>(&u) = h; return u;
}
__device__ __forceinline__ float fexp2(float x) {
    float r;
    asm("ex2.approx.f32 %0, %1;" : "=f"(r) : "f"(x));
    return r;
}

// ---------------------------------------------------------------------------
// Pre-round pass: fp32 inputs -> fp16 copies
// ---------------------------------------------------------------------------
__global__ __launch_bounds__(256) void round_f16_kernel(
    const float4* __restrict__ a, uint2* __restrict__ da, int na4,
    const float4* __restrict__ b, uint2* __restrict__ db, int nb4,
    const float4* __restrict__ c, uint2* __restrict__ dc, int nc4)
{
    int total = na4 + nb4 + nc4;
    for (int i = blockIdx.x * blockDim.x + threadIdx.x; i < total;
         i += gridDim.x * blockDim.x) {
        const float4* s; uint2* d; int j;
        if (i < na4)            { s = a; d = da; j = i; }
        else if (i < na4 + nb4) { s = b; d = db; j = i - na4; }
        else                    { s = c; d = dc; j = i - na4 - nb4; }
        float4 v = s[j];
        d[j] = make_uint2(h2u(__floats2half2_rn(v.x, v.y)),
                          h2u(__floats2half2_rn(v.z, v.w)));
    }
}

// ---------------------------------------------------------------------------
// fp16 GEMM: C[M,N] = A[M,K] * B[N,K]^T, fp32 accum. Templated on CTA-N and
// warp count; warp tile FIXED at 64x64 (the proven shape).
//   TBN=256, 8 warps : GEMM3
//   TBN=384, 12 warps: 3 warps/SMSP (GEMM1, R15 winner)
// BK=64, 3-stage cp.async, scalar-LDS fragments.
// round_out: fp16 output with cols<1024 scaled by QSCALE (Q); else fp32 out.
// ---------------------------------------------------------------------------
#define BM 128
#define BK 64
#define HSTR 72                          // halves per row (64 + 8 pad)
#define WSTR 36                          // 32-bit words per row
#define A_TILE_H (BM * HSTR)             // 9216 halves
#define NSTAGE 3

template<int TBN, int TTHREADS>
__global__ __launch_bounds__(TTHREADS) void gemm_f16(
    const __half* __restrict__ A, const __half* __restrict__ Bw,
    void* __restrict__ Cv, int M, int N, int K, int round_out)
{
    constexpr int B_TILE_H = TBN * HSTR;
    constexpr int STAGE_H = A_TILE_H + B_TILE_H;

    extern __shared__ __half smh[];
    const int tid = threadIdx.x;
    const int wid = tid >> 5, lane = tid & 31;
    const int g = lane >> 2, tg = lane & 3;
    const int m0 = blockIdx.y * BM, n0 = blockIdx.x * TBN;
    const int wm = (wid & 1) * 64, wn = (wid >> 1) * 64;

    float acc[4][8][4];
#pragma unroll
    for (int mi = 0; mi < 4; mi++)
#pragma unroll
        for (int ni = 0; ni < 8; ni++)
#pragma unroll
            for (int j = 0; j < 4; j++) acc[mi][ni][j] = 0.f;

    const int KT = K / BK;

    auto load_stage = [&](int kt) {
        __half* base = smh + (kt % NSTAGE) * STAGE_H;
        const __half* Ag = A + (size_t)m0 * K + kt * BK;
        const __half* Bg = Bw + (size_t)n0 * K + kt * BK;
        for (int c = tid; c < BM * 8; c += TTHREADS) {      // A chunks
            int row = c >> 3, col = c & 7;
            cp16(smem_u32(base + row * HSTR + col * 8),
                 Ag + (size_t)row * K + col * 8);
        }
        __half* bb = base + A_TILE_H;
        for (int c = tid; c < TBN * 8; c += TTHREADS) {     // B chunks
            int row = c >> 3, col = c & 7;
            cp16(smem_u32(bb + row * HSTR + col * 8),
                 Bg + (size_t)row * K + col * 8);
        }
    };

    load_stage(0); CP_COMMIT();
    load_stage(1); CP_COMMIT();

    for (int kt = 0; kt < KT; kt++) {
        CP_WAIT1();            // stage kt resident
        __syncthreads();       // all warps finished stage kt-1
        if (kt + 2 < KT) load_stage(kt + 2);
        CP_COMMIT();           // keep group counts aligned

        const uint32_t* As32 = reinterpret_cast<const uint32_t*>(
            smh + (kt % NSTAGE) * STAGE_H);
        const uint32_t* Bs32 = As32 + A_TILE_H / 2;

#pragma unroll
        for (int kk = 0; kk < 4; kk++) {     // 4 k16 steps per tile
            const int k0w = kk * 8;
            uint32_t af[4][4], bf[8][2];
#pragma unroll
            for (int mi = 0; mi < 4; mi++) {
                int r0 = wm + mi * 16 + g;
                af[mi][0] = As32[r0 * WSTR + k0w + tg];
                af[mi][1] = As32[(r0 + 8) * WSTR + k0w + tg];
                af[mi][2] = As32[r0 * WSTR + k0w + tg + 4];
                af[mi][3] = As32[(r0 + 8) * WSTR + k0w + tg + 4];
            }
#pragma unroll
            for (int ni = 0; ni < 8; ni++) {
                int rn = wn + ni * 8 + g;
                bf[ni][0] = Bs32[rn * WSTR + k0w + tg];
                bf[ni][1] = Bs32[rn * WSTR + k0w + tg + 4];
            }
#pragma unroll
            for (int mi = 0; mi < 4; mi++)
#pragma unroll
                for (int ni = 0; ni < 8; ni++)
                    mma_f16(acc[mi][ni], af[mi], bf[ni]);
        }
    }

    if (round_out) {
        __half* Ch = (__half*)Cv;
#pragma unroll
        for (int mi = 0; mi < 4; mi++) {
            int r0 = m0 + wm + mi * 16 + g;
#pragma unroll
            for (int ni = 0; ni < 8; ni++) {
                int cc = n0 + wn + ni * 8 + 2 * tg;
                float sc = (cc < CMODEL) ? QSCALE : 1.f;   // Q: 1/8 * log2(e)
                *reinterpret_cast<__half2*>(&Ch[(size_t)r0 * N + cc]) =
                    __floats2half2_rn(acc[mi][ni][0] * sc, acc[mi][ni][1] * sc);
                *reinterpret_cast<__half2*>(&Ch[(size_t)(r0 + 8) * N + cc]) =
                    __floats2half2_rn(acc[mi][ni][2] * sc, acc[mi][ni][3] * sc);
            }
        }
    } else {
        float* Cf = (float*)Cv;
#pragma unroll
        for (int mi = 0; mi < 4; mi++) {
            int r0 = m0 + wm + mi * 16 + g;
#pragma unroll
            for (int ni = 0; ni < 8; ni++) {
                int cc = n0 + wn + ni * 8 + 2 * tg;
                *reinterpret_cast<float2*>(&Cf[(size_t)r0 * N + cc]) =
                    make_float2(acc[mi][ni][0], acc[mi][ni][1]);
                *reinterpret_cast<float2*>(&Cf[(size_t)(r0 + 8) * N + cc]) =
                    make_float2(acc[mi][ni][2], acc[mi][ni][3]);
            }
        }
    }
}

#define GSMEM_256 (NSTAGE * (A_TILE_H + 256 * HSTR) * 2)   // 165888 bytes
#define GSMEM_384 (NSTAGE * (A_TILE_H + 384 * HSTR) * 2)   // 221184 bytes

// ---------------------------------------------------------------------------
// fp16 tensor-core flash attention (causal), exp2 softmax, register-resident
// P. NEW: BR=64, 4 warps/CTA, 4 CTAs/SM (smem 46KB each). Per-warp code
// identical to the R13/R15 winner (16 q-rows/warp); only CTA granularity
// changes: finer sync domains, 4 independent CTA streams per SM, better
// triangular load balance across 1024 CTAs.
// ---------------------------------------------------------------------------
#define BR 64
#define BC 64
#define ATHREADS 128
#define AQSTR 72                              // halves (36 words)
#define OFF_Q 0
#define OFF_K (BR * AQSTR)                    // 4608 halves
#define OFF_V (OFF_K + 2 * BC * AQSTR)        // 13824
#define ATTN_SMEM_H (OFF_V + 2 * BC * AQSTR)  // 23040 halves
#define ATTN_SMEM (ATTN_SMEM_H * 2)           // 46080 bytes

__global__ __launch_bounds__(ATHREADS, 4) void attn_f16_kernel()
{
    extern __shared__ __half smh[];
    const int tid = threadIdx.x;
    const int wid = tid >> 5, lane = tid & 31;
    const int g = lane >> 2, tg = lane & 3;
    const int ib = (int)gridDim.x - 1 - (int)blockIdx.x;   // big tiles first
    const int h = blockIdx.y, b = blockIdx.z;
    const int ibase = ib * BR;
    const int hoff = h * DHEAD;
    const int wm = wid * 16;

    // ---- async load Q tile + KV tile 0 ----
    {
        const __half* Qg = g_qkvh + (size_t)(b * T_ + ibase) * F3 + hoff;
        for (int i = tid; i < BR * 8; i += ATHREADS) {
            int row = i >> 3, c = i & 7;
            cp16(smem_u32(smh + OFF_Q + row * AQSTR + c * 8),
                 Qg + (size_t)row * F3 + c * 8);
        }
    }
    auto load_kv = [&](int jb) {
        int buf = jb & 1;
        const __half* Kg = g_qkvh + (size_t)(b * T_ + jb * BC) * F3 + CMODEL + hoff;
        const __half* Vg = Kg + CMODEL;
        __half* Kb = smh + OFF_K + buf * BC * AQSTR;
        __half* Vb = smh + OFF_V + buf * BC * AQSTR;
        for (int i = tid; i < BC * 8; i += ATHREADS) {
            int row = i >> 3, c = i & 7;
            cp16(smem_u32(Kb + row * AQSTR + c * 8), Kg + (size_t)row * F3 + c * 8);
            cp16(smem_u32(Vb + row * AQSTR + c * 8), Vg + (size_t)row * F3 + c * 8);
        }
    };
    load_kv(0);
    CP_COMMIT();

    const int NT = ib + 1;        // number of 64-key tiles (causal)

    float m0 = -1e30f, m1 = -1e30f, l0 = 0.f, l1 = 0.f;
    float o[8][4];
#pragma unroll
    for (int ni = 0; ni < 8; ni++)
#pragma unroll
        for (int j = 0; j < 4; j++) o[ni][j] = 0.f;

    // Q fragments register-resident
    CP_WAIT0();
    __syncthreads();
    uint32_t qf[4][4];
    {
        const uint32_t* Qs32 = reinterpret_cast<const uint32_t*>(smh + OFF_Q);
#pragma unroll
        for (int kk = 0; kk < 4; kk++) {
            qf[kk][0] = Qs32[(wm + g) * WSTR + kk * 8 + tg];
            qf[kk][1] = Qs32[(wm + g + 8) * WSTR + kk * 8 + tg];
            qf[kk][2] = Qs32[(wm + g) * WSTR + kk * 8 + tg + 4];
            qf[kk][3] = Qs32[(wm + g + 8) * WSTR + kk * 8 + tg + 4];
        }
    }

    for (int jb = 0; jb < NT; jb++) {
        if (jb > 0) {
            CP_WAIT0();        // KV jb resident
            __syncthreads();   // all warps done with buffer (jb-1)&1
        }
        if (jb + 1 < NT) {
            load_kv(jb + 1);
            CP_COMMIT();
        }

        const int jbase = jb * BC;
        const bool skip = (jbase > ibase + wm + 15);
        if (!skip) {
            const __half* Vb = smh + OFF_V + (jb & 1) * BC * AQSTR;
            const uint32_t* Kb32 = reinterpret_cast<const uint32_t*>(
                smh + OFF_K + (jb & 1) * BC * AQSTR);

            // ---- S = Q K^T (scores already in log2 domain) ----
            float s[8][4];
#pragma unroll
            for (int ni = 0; ni < 8; ni++)
#pragma unroll
                for (int j = 0; j < 4; j++) s[ni][j] = 0.f;
#pragma unroll
            for (int kk = 0; kk < 4; kk++) {
                const int k0w = kk * 8;
#pragma unroll
                for (int ni = 0; ni < 8; ni++) {
                    uint32_t bfr[2];
                    bfr[0] = Kb32[(ni * 8 + g) * WSTR + k0w + tg];
                    bfr[1] = Kb32[(ni * 8 + g) * WSTR + k0w + tg + 4];
                    mma_f16(s[ni], qf[kk], bfr);
                }
            }

            // ---- causal mask ----
            const int qr0 = ibase + wm + g;
            const int qr1 = qr0 + 8;
            const bool full = (jbase + BC - 1 <= ibase + wm);
            if (!full) {
#pragma unroll
                for (int ni = 0; ni < 8; ni++) {
                    int kc = jbase + ni * 8 + 2 * tg;
                    if (kc > qr0)     s[ni][0] = -1e30f;
                    if (kc + 1 > qr0) s[ni][1] = -1e30f;
                    if (kc > qr1)     s[ni][2] = -1e30f;
                    if (kc + 1 > qr1) s[ni][3] = -1e30f;
                }
            }

            // ---- online softmax (exp2 domain), P packed in registers ----
            float rm0 = -1e30f, rm1 = -1e30f;
#pragma unroll
            for (int ni = 0; ni < 8; ni++) {
                rm0 = fmaxf(rm0, fmaxf(s[ni][0], s[ni][1]));
                rm1 = fmaxf(rm1, fmaxf(s[ni][2], s[ni][3]));
            }
            rm0 = fmaxf(rm0, __shfl_xor_sync(0xffffffffu, rm0, 1));
            rm0 = fmaxf(rm0, __shfl_xor_sync(0xffffffffu, rm0, 2));
            rm1 = fmaxf(rm1, __shfl_xor_sync(0xffffffffu, rm1, 1));
            rm1 = fmaxf(rm1, __shfl_xor_sync(0xffffffffu, rm1, 2));
            float mn0 = fmaxf(m0, rm0), mn1 = fmaxf(m1, rm1);
            float c0 = fexp2(m0 - mn0), c1 = fexp2(m1 - mn1);
            m0 = mn0; m1 = mn1;

            uint32_t ph[8][2];   // [ni][0] rows g (p0,p1); [1] rows g+8
            float ls0 = 0.f, ls1 = 0.f;
#pragma unroll
            for (int ni = 0; ni < 8; ni++) {
                float p0 = fexp2(s[ni][0] - mn0);
                float p1 = fexp2(s[ni][1] - mn0);
                float p2 = fexp2(s[ni][2] - mn1);
                float p3 = fexp2(s[ni][3] - mn1);
                ls0 += p0 + p1; ls1 += p2 + p3;
                ph[ni][0] = h2u(__floats2half2_rn(p0, p1));
                ph[ni][1] = h2u(__floats2half2_rn(p2, p3));
            }
            ls0 += __shfl_xor_sync(0xffffffffu, ls0, 1);
            ls0 += __shfl_xor_sync(0xffffffffu, ls0, 2);
            ls1 += __shfl_xor_sync(0xffffffffu, ls1, 1);
            ls1 += __shfl_xor_sync(0xffffffffu, ls1, 2);
            l0 = l0 * c0 + ls0;
            l1 = l1 * c1 + ls1;
#pragma unroll
            for (int ni = 0; ni < 8; ni++) {
                o[ni][0] *= c0; o[ni][1] *= c0;
                o[ni][2] *= c1; o[ni][3] *= c1;
            }

            // ---- O += P V (P A-frags direct from registers) ----
#pragma unroll
            for (int kk = 0; kk < 4; kk++) {       // key blocks of 16
                const int k0 = kk * 16;
                uint32_t ap[4] = { ph[2 * kk][0], ph[2 * kk][1],
                                   ph[2 * kk + 1][0], ph[2 * kk + 1][1] };
#pragma unroll
                for (int np = 0; np < 4; np++) {   // d-blocks of 16 (2 ni each)
                    uint32_t vr[4];
                    const __half* vaddr = (lane < 16)
                        ? &Vb[(k0 + lane) * AQSTR + np * 16]
                        : &Vb[(k0 + lane - 16) * AQSTR + np * 16 + 8];
                    ldsm_x4_trans(vr, smem_u32(vaddr));
                    mma_f16(o[2 * np],     ap, vr);
                    mma_f16(o[2 * np + 1], ap, vr + 2);
                }
            }
        }
    }

    // ---- epilogue: O / l -> fp16 g_attnh ----
    const float inv0 = 1.f / l0, inv1 = 1.f / l1;
    __half* O0 = g_attnh + (size_t)(b * T_ + ibase + wm + g) * CMODEL + hoff;
    __half* O1 = O0 + 8 * CMODEL;
#pragma unroll
    for (int ni = 0; ni < 8; ni++) {
        int cc = ni * 8 + 2 * tg;
        *reinterpret_cast<__half2*>(O0 + cc) =
            __floats2half2_rn(o[ni][0] * inv0, o[ni][1] * inv0);
        *reinterpret_cast<__half2*>(O1 + cc) =
            __floats2half2_rn(o[ni][2] * inv1, o[ni][3] * inv1);
    }
}

// ---------------------------------------------------------------------------
// Launch
// ---------------------------------------------------------------------------
extern "C" void kernel_launch(void* const* d_in, const int* in_sizes, int n_in,
                              void* d_out, int out_size)
{
    const float* x    = (const float*)d_in[0];
    const float* Wqkv = (const float*)d_in[1];
    const float* Wout = (const float*)d_in[2];
    float* out = (float*)d_out;

    __half *qkvh, *attnh, *xh, *wqh, *woh;
    cudaGetSymbolAddress((void**)&qkvh, g_qkvh);
    cudaGetSymbolAddress((void**)&attnh, g_attnh);
    cudaGetSymbolAddress((void**)&xh, g_xh);
    cudaGetSymbolAddress((void**)&wqh, g_wqh);
    cudaGetSymbolAddress((void**)&woh, g_woh);

    cudaFuncSetAttribute(gemm_f16<384, 384>,
                         cudaFuncAttributeMaxDynamicSharedMemorySize, GSMEM_384);
    cudaFuncSetAttribute(gemm_f16<256, 256>,
                         cudaFuncAttributeMaxDynamicSharedMemorySize, GSMEM_256);
    cudaFuncSetAttribute(attn_f16_kernel,
                         cudaFuncAttributeMaxDynamicSharedMemorySize, ATTN_SMEM);

    // 0) pre-round inputs to fp16
    round_f16_kernel<<<1024, 256>>>(
        (const float4*)x,    (uint2*)xh,  (NTOK * CMODEL) / 4,
        (const float4*)Wqkv, (uint2*)wqh, (F3 * CMODEL) / 4,
        (const float4*)Wout, (uint2*)woh, (CMODEL * CMODEL) / 4);

    // 1) qkv = x @ Wqkv^T  (128x384 CTA, 12 warps, R15 winner)
    gemm_f16<384, 384><<<dim3(F3 / 384, NTOK / BM), 384, GSMEM_384>>>(
        xh, wqh, qkvh, NTOK, F3, CMODEL, 1);

    // 2) causal flash attention (BR=64, 4 warps, 4 CTAs/SM)
    attn_f16_kernel<<<dim3(T_ / BR, NHEADS, B_), ATHREADS, ATTN_SMEM>>>();

    // 3) out = attn @ Wout^T  (proven 128x256 / 8-warp config)
    gemm_f16<256, 256><<<dim3(CMODEL / 256, NTOK / BM), 256, GSMEM_256>>>(
        attnh, woh, out, NTOK, CMODEL, CMODEL, 0);
}